// round 16
// baseline (speedup 1.0000x reference)
#include <cuda_runtime.h>
#include <cuda_bf16.h>
#include <cuda_fp16.h>
#include <cstdint>

// ---------------------------------------------------------------------------
// FiSHAttention: B=8, N=1024, dim=p=768, HEAD_DIM=64, K_GLOBAL=4, H_eff=12
// Pure-fp16 tensor pipeline + dual streams + MUFU exp + fully double-buffered
// attention (stage & V prefetched a FULL tile ahead; 1 CTA/SM, 5.2 waves).
// Error model (calibrated): out_err ~= 0.44*unit-rounding/fp16 operand;
// measured 5.2e-4, margin ~1.9x.
// ---------------------------------------------------------------------------

#define B_SZ   8
#define N_SEQ  1024
#define DIM    768
#define KG     4
#define HD     64
#define HEFF   12

__device__ __half g_x16[B_SZ * N_SEQ * DIM];
__device__ __half g_Wq16[512 * DIM];
__device__ __half g_Wv16[DIM * DIM];
__device__ __half g_Wp16[DIM * DIM];
__device__ __half g_Yh [B_SZ * N_SEQ * 512];
__device__ __half g_V16[B_SZ * N_SEQ * DIM];
__device__ __half g_c16[B_SZ * N_SEQ * DIM];
__device__ __half g_S4h[(size_t)B_SZ * KG * N_SEQ * N_SEQ];   // 64 MB
__device__ __half g_Vt [(size_t)B_SZ * HEFF * HD * N_SEQ];

// ------------------------------ helpers ------------------------------------
__device__ __forceinline__ uint32_t smem_u32(const void* p) {
    uint32_t a;
    asm("{ .reg .u64 t; cvta.to.shared.u64 t, %1; cvt.u32.u64 %0, t; }"
        : "=r"(a) : "l"(p));
    return a;
}
__device__ __forceinline__ void ldsm_x4(uint32_t& r0, uint32_t& r1,
                                        uint32_t& r2, uint32_t& r3, uint32_t addr) {
    asm volatile("ldmatrix.sync.aligned.m8n8.x4.shared.b16 {%0,%1,%2,%3}, [%4];"
        : "=r"(r0), "=r"(r1), "=r"(r2), "=r"(r3) : "r"(addr));
}
__device__ __forceinline__ void mma16816h(float* c, const uint32_t* a,
                                          const uint32_t* b) {
    asm volatile("mma.sync.aligned.m16n8k16.row.col.f32.f16.f16.f32 "
        "{%0,%1,%2,%3}, {%4,%5,%6,%7}, {%8,%9}, {%0,%1,%2,%3};"
        : "+f"(c[0]), "+f"(c[1]), "+f"(c[2]), "+f"(c[3])
        : "r"(a[0]), "r"(a[1]), "r"(a[2]), "r"(a[3]), "r"(b[0]), "r"(b[1]));
}
__device__ __forceinline__ void cp_async16(uint32_t s, const void* g) {
    asm volatile("cp.async.cg.shared.global [%0], [%1], 16;" :: "r"(s), "l"(g));
}
__device__ __forceinline__ void cp_commit() {
    asm volatile("cp.async.commit_group;" ::: "memory");
}
template<int N> __device__ __forceinline__ void cp_wait() {
    asm volatile("cp.async.wait_group %0;" :: "n"(N) : "memory");
}
__device__ __forceinline__ uint32_t pack_h2(float x, float y) {
    return ((uint32_t)__half_as_ushort(__float2half(y)) << 16)
         | __half_as_ushort(__float2half(x));
}
__device__ __forceinline__ float mufu_exp2(float y) {
    float r;
    asm("ex2.approx.f32 %0, %1;" : "=f"(r) : "f"(y));
    return r;
}

#define BKC  32
#define TSTR 40
#define GTB  (128 * TSTR * 2)
#define GSMEM (4 * GTB)

// ===========================================================================
// cvt16: f32 -> fp16 elementwise.
// ===========================================================================
__global__ __launch_bounds__(256) void cvt16(
    const float* __restrict__ in, __half* __restrict__ o, int n4)
{
    int i = blockIdx.x * 256 + threadIdx.x;
    if (i >= n4) return;
    float4 v = ((const float4*)in)[i];
    uint2 h;
    h.x = pack_h2(v.x, v.y);
    h.y = pack_h2(v.z, v.w);
    ((uint2*)o)[i] = h;
}

// ===========================================================================
// Unified pure-fp16 TN GEMM, cp.async 2-stage double-buffered.
// ===========================================================================
__global__ __launch_bounds__(256) void gemm16(
    const __half* __restrict__ A, const __half* __restrict__ B,
    float* __restrict__ Cf, __half* __restrict__ Ch,
    const float* __restrict__ bias,
    int K, int lda, int ldb, int ldc, float alpha,
    long sAo, long sAi, long sBo, long sBi, long sC, int innerMod)
{
    {
        int z = blockIdx.z;
        int outer = z / innerMod;
        int inner = z - outer * innerMod;
        A += (long)outer * sAo + (long)inner * sAi;
        B += (long)outer * sBo + (long)inner * sBi;
        if (Cf) Cf += (long)z * sC;
        if (Ch) Ch += (long)z * sC;
    }
    const int row0 = blockIdx.y * 128;
    const int col0 = blockIdx.x * 128;

    extern __shared__ char dsm[];
    const uint32_t base = smem_u32(dsm);

    const int tid  = threadIdx.x;
    const int wid  = tid >> 5;
    const int lane = tid & 31;
    const int wm   = wid >> 1;
    const int wn   = wid & 1;
    const int a_r = lane & 15;
    const int a_k = (lane >> 4) << 3;
    const int b_r = (lane & 7) + ((lane >> 4) << 3);
    const int b_k = ((lane >> 3) & 1) << 3;

    float acc[2][8][4];
    #pragma unroll
    for (int i = 0; i < 2; i++)
        #pragma unroll
        for (int j = 0; j < 8; j++)
            #pragma unroll
            for (int q = 0; q < 4; q++) acc[i][j][q] = 0.0f;

    auto issue = [&](int t) {
        const uint32_t sb = base + (uint32_t)(t & 1) * (2 * GTB);
        #pragma unroll
        for (int it = 0; it < 2; it++) {
            int idx = it * 256 + tid;
            int r = idx >> 2, q = (idx & 3) << 3;
            cp_async16(sb + (uint32_t)(r * TSTR + q) * 2,
                       &A[(long)(row0 + r) * lda + t * BKC + q]);
        }
        #pragma unroll
        for (int it = 0; it < 2; it++) {
            int idx = it * 256 + tid;
            int r = idx >> 2, q = (idx & 3) << 3;
            cp_async16(sb + GTB + (uint32_t)(r * TSTR + q) * 2,
                       &B[(long)(col0 + r) * ldb + t * BKC + q]);
        }
        cp_commit();
    };

    const int nch = K / BKC;
    issue(0);

    for (int t = 0; t < nch; t++) {
        if (t + 1 < nch) {
            issue(t + 1);
            cp_wait<1>();
        } else {
            cp_wait<0>();
        }
        __syncthreads();

        const uint32_t uA = base + (uint32_t)(t & 1) * (2 * GTB);
        const uint32_t uB = uA + GTB;

        #pragma unroll
        for (int ks = 0; ks < 2; ks++) {
            const int k0 = ks * 16;
            const uint32_t aoff = (uint32_t)((wm * 32 + a_r) * TSTR + k0 + a_k) * 2;
            const uint32_t boff = (uint32_t)((wn * 64 + b_r) * TSTR + k0 + b_k) * 2;
            uint32_t af[2][4];
            ldsm_x4(af[0][0], af[0][1], af[0][2], af[0][3], uA + aoff);
            ldsm_x4(af[1][0], af[1][1], af[1][2], af[1][3], uA + aoff + 16 * TSTR * 2);
            uint32_t bv[8][2];
            #pragma unroll
            for (int nb = 0; nb < 4; nb++)
                ldsm_x4(bv[2*nb][0], bv[2*nb][1], bv[2*nb+1][0], bv[2*nb+1][1],
                        uB + boff + nb * 16 * TSTR * 2);
            #pragma unroll
            for (int mf = 0; mf < 2; mf++)
                #pragma unroll
                for (int nf = 0; nf < 8; nf++)
                    mma16816h(acc[mf][nf], af[mf], bv[nf]);
        }
        __syncthreads();
    }

    const int qrow = lane >> 2;
    const int qcol = (lane & 3) << 1;
    #pragma unroll
    for (int mf = 0; mf < 2; mf++)
        #pragma unroll
        for (int half = 0; half < 2; half++) {
            long r = row0 + wm * 32 + mf * 16 + half * 8 + qrow;
            #pragma unroll
            for (int nf = 0; nf < 8; nf++) {
                int n = col0 + wn * 64 + nf * 8 + qcol;
                float ox = alpha * acc[mf][nf][half * 2 + 0];
                float oy = alpha * acc[mf][nf][half * 2 + 1];
                if (Cf) {
                    float2 o;
                    o.x = ox; o.y = oy;
                    if (bias) { o.x += bias[n]; o.y += bias[n + 1]; }
                    *(float2*)&Cf[r * ldc + n] = o;
                } else {
                    *(uint32_t*)&Ch[r * ldc + n] = pack_h2(ox, oy);
                }
            }
        }
}

// ===========================================================================
// V transpose (fp16 in/out).
// ===========================================================================
__global__ __launch_bounds__(256) void vconvert(
    const __half* __restrict__ V, __half* __restrict__ Vt)
{
    const int j0   = blockIdx.x * 64;
    const int bhid = blockIdx.y;
    const int b    = bhid / HEFF;
    const int h    = bhid - b * HEFF;

    __shared__ __half sT[64][72];
    const int tid = threadIdx.x;

    #pragma unroll
    for (int it = 0; it < 4; it++) {
        int e = it * 256 + tid;
        int j = e >> 4, dq = (e & 15) << 2;
        uint2 u = *(const uint2*)&V[((long)b * N_SEQ + j0 + j) * DIM + h * HD + dq];
        __half2 a = *(__half2*)&u.x;
        __half2 c = *(__half2*)&u.y;
        sT[dq + 0][j] = __low2half(a);  sT[dq + 1][j] = __high2half(a);
        sT[dq + 2][j] = __low2half(c);  sT[dq + 3][j] = __high2half(c);
    }
    __syncthreads();

    const int d = tid >> 2, jseg = (tid & 3) << 4;
    size_t dst = ((size_t)bhid * HD + d) * N_SEQ + j0 + jseg;
    *(uint4*)&Vt[dst]     = *(uint4*)&sT[d][jseg];
    *(uint4*)&Vt[dst + 8] = *(uint4*)&sT[d][jseg + 8];
}

// ===========================================================================
// Attention v9: fully double-buffered (stage + V prefetched one full tile
// ahead), MUFU exp, 2 heads/CTA, 1 CTA/SM. Grid (16, 6, 8), 256 threads.
// smem: V [parity][head] 4x9216 | P [head] 2x9216 | stage 2 x (4x64x64 fp16,
// unpadded; conflict-free for the LDS.128 phase-A pattern) | sums/mix.
// Loop: wait(oldest) -> sync -> phaseA(t) -> sync -> MMA(t) -> sync ->
//       issue(t+2)   (loads get a FULL tile in flight)
// ===========================================================================
#define PBY 9216
#define SPLB 8192                    // stage plane bytes (64x64 fp16)
#define SBUFB (4 * SPLB)             // 32768 per stage buffer
#define OFF_V 0
#define OFF_P (4 * PBY)              // 36864
#define OFF_S (6 * PBY)              // 55296
#define OFF_SUM (OFF_S + 2 * SBUFB)  // 120832
#define OFF_MIX (OFF_SUM + 512)
#define ATTN_SMEM (OFF_MIX + 64)

__global__ __launch_bounds__(256, 1) void attn_kernel(
    const __half* __restrict__ S4, const __half* __restrict__ Vt,
    const float* __restrict__ mixl, __half* __restrict__ ctx)
{
    const int ib = blockIdx.x;
    const int hg = blockIdx.y;
    const int b  = blockIdx.z;

    extern __shared__ char sm[];
    const uint32_t sb = smem_u32(sm);
    float* sSum = (float*)(sm + OFF_SUM);
    float* sMix = (float*)(sm + OFF_MIX);

    const int tid  = threadIdx.x;
    const int wid  = tid >> 5;
    const int lane = tid & 31;
    const int wr   = wid >> 1;
    const int wc   = wid & 1;
    const int a_r  = lane & 15;
    const int a_k  = (lane >> 4) << 3;
    const int b_r  = (lane & 7) + ((lane >> 4) << 3);
    const int b_k  = ((lane >> 3) & 1) << 3;

    if (tid < 128) sSum[tid] = 0.0f;
    if (tid < 8) {
        int hh = tid >> 2, k = tid & 3;
        const float* ml = mixl + (hg * 2 + hh) * 4;
        float l0 = ml[0], l1 = ml[1], l2 = ml[2], l3 = ml[3];
        const float L2E = 1.4426950408889634f;
        float m  = fmaxf(fmaxf(l0, l1), fmaxf(l2, l3));
        float e0 = mufu_exp2((l0 - m) * L2E), e1 = mufu_exp2((l1 - m) * L2E);
        float e2 = mufu_exp2((l2 - m) * L2E), e3 = mufu_exp2((l3 - m) * L2E);
        float s  = e0 + e1 + e2 + e3;
        float mine = (k == 0) ? e0 : (k == 1) ? e1 : (k == 2) ? e2 : e3;
        sMix[hh * 4 + k] = (mine / s) * L2E;
    }

    const int i0   = ib * 64;
    const int arow = tid >> 2;
    const int aq   = tid & 3;
    const __half* S4b = S4 + (size_t)b * KG * N_SEQ * N_SEQ;
    const long   PL  = (long)N_SEQ * N_SEQ;
    const size_t vbase0 = ((size_t)(b * HEFF + hg * 2 + 0)) * HD * N_SEQ;
    const size_t vbase1 = ((size_t)(b * HEFF + hg * 2 + 1)) * HD * N_SEQ;

    auto issue_tile = [&](int jt) {
        const int j0 = jt * 64;
        const int parity = jt & 1;
        #pragma unroll
        for (int it = 0; it < 4; it++) {           // V: 1024 x 16B
            int idx = it * 256 + tid;
            int hh = idx >> 9;
            int r  = (idx >> 3) & 63;
            int q  = idx & 7;
            size_t so = (hh ? vbase1 : vbase0) + (size_t)r * N_SEQ + j0 + q * 8;
            cp_async16(sb + OFF_V + (uint32_t)(parity * 2 + hh) * PBY
                          + (uint32_t)(r * 72 + q * 8) * 2, &Vt[so]);
        }
        #pragma unroll
        for (int it = 0; it < 8; it++) {           // stage: 2048 x 16B
            int idx = it * 256 + tid;
            int p  = idx >> 9;
            int r  = (idx >> 3) & 63;
            int q  = idx & 7;
            const __half* g = S4b + (size_t)p * PL
                            + (long)(i0 + r) * N_SEQ + j0 + q * 8;
            cp_async16(sb + OFF_S + (uint32_t)parity * SBUFB
                          + (uint32_t)(p * SPLB) + (uint32_t)(r * 64 + q * 8) * 2, g);
        }
        cp_commit();
    };

    float acc[2][4][4];
    #pragma unroll
    for (int i = 0; i < 2; i++)
        #pragma unroll
        for (int j = 0; j < 4; j++)
            #pragma unroll
            for (int q = 0; q < 4; q++) acc[i][j][q] = 0.0f;

    issue_tile(0);
    issue_tile(1);

    for (int t = 0; t < 16; t++) {
        if (t < 15) cp_wait<1>(); else cp_wait<0>();
        __syncthreads();   // tile t data ready & visible; prev MMA done

        // ---- phase A: wide LDS.128 reads, combine + MUFU exp2, P fp16 ------
        {
            const float mx00 = sMix[0], mx01 = sMix[1], mx02 = sMix[2], mx03 = sMix[3];
            const float mx10 = sMix[4], mx11 = sMix[5], mx12 = sMix[6], mx13 = sMix[7];
            const char* sst = sm + OFF_S + (uint32_t)(t & 1) * SBUFB
                            + (uint32_t)(arow * 64 + aq * 16) * 2;
            uint32_t pr[4][8];
            #pragma unroll
            for (int p = 0; p < 4; p++) {
                *(uint4*)&pr[p][0] = *(const uint4*)(sst + p * SPLB);
                *(uint4*)&pr[p][4] = *(const uint4*)(sst + p * SPLB + 16);
            }
            float s0 = 0.0f, s1 = 0.0f;
            #pragma unroll
            for (int c = 0; c < 4; c++) {
                float2 fa0 = __half22float2(*(__half2*)&pr[0][2*c]);
                float2 fa1 = __half22float2(*(__half2*)&pr[0][2*c+1]);
                float2 f10 = __half22float2(*(__half2*)&pr[1][2*c]);
                float2 f11 = __half22float2(*(__half2*)&pr[1][2*c+1]);
                float2 f20 = __half22float2(*(__half2*)&pr[2][2*c]);
                float2 f21 = __half22float2(*(__half2*)&pr[2][2*c+1]);
                float2 f30 = __half22float2(*(__half2*)&pr[3][2*c]);
                float2 f31 = __half22float2(*(__half2*)&pr[3][2*c+1]);
                const uint32_t po = (uint32_t)(arow * 72 + aq * 16 + c * 4) * 2;
                #pragma unroll
                for (int hh = 0; hh < 2; hh++) {
                    float m0 = hh ? mx10 : mx00, m1 = hh ? mx11 : mx01;
                    float m2 = hh ? mx12 : mx02, m3 = hh ? mx13 : mx03;
                    float q0 = mufu_exp2(fmaf(m3, f30.x, fmaf(m2, f20.x, fmaf(m1, f10.x, m0 * fa0.x))));
                    float q1 = mufu_exp2(fmaf(m3, f30.y, fmaf(m2, f20.y, fmaf(m1, f10.y, m0 * fa0.y))));
                    float q2 = mufu_exp2(fmaf(m3, f31.x, fmaf(m2, f21.x, fmaf(m1, f11.x, m0 * fa1.x))));
                    float q3 = mufu_exp2(fmaf(m3, f31.y, fmaf(m2, f21.y, fmaf(m1, f11.y, m0 * fa1.y))));
                    if (hh) s1 += (q0 + q1) + (q2 + q3);
                    else    s0 += (q0 + q1) + (q2 + q3);
                    uint2 hv;
                    hv.x = pack_h2(q0, q1);
                    hv.y = pack_h2(q2, q3);
                    *(uint2*)(sm + OFF_P + hh * PBY + po) = hv;
                }
            }
            s0 += __shfl_xor_sync(0xffffffffu, s0, 1);
            s0 += __shfl_xor_sync(0xffffffffu, s0, 2);
            s1 += __shfl_xor_sync(0xffffffffu, s1, 1);
            s1 += __shfl_xor_sync(0xffffffffu, s1, 2);
            if (aq == 0) {
                sSum[arow]      += s0;
                sSum[64 + arow] += s1;
            }
        }
        __syncthreads();   // P visible

        // ---- MMA: both heads, 1-pass fp16 (P @ V[parity t]) ----------------
        #pragma unroll
        for (int hh = 0; hh < 2; hh++) {
            const uint32_t uP = sb + OFF_P + hh * PBY;
            const uint32_t uV = sb + OFF_V + (uint32_t)((t & 1) * 2 + hh) * PBY;
            #pragma unroll
            for (int ks = 0; ks < 4; ks++) {
                const int k0 = ks * 16;
                const uint32_t aoff = (uint32_t)((wr * 16 + a_r) * 72 + k0 + a_k) * 2;
                const uint32_t boff = (uint32_t)((wc * 32 + b_r) * 72 + k0 + b_k) * 2;
                uint32_t ah[4];
                ldsm_x4(ah[0], ah[1], ah[2], ah[3], uP + aoff);
                uint32_t bv[4][2];
                #pragma unroll
                for (int nb = 0; nb < 2; nb++)
                    ldsm_x4(bv[2*nb][0], bv[2*nb][1], bv[2*nb+1][0], bv[2*nb+1][1],
                            uV + boff + nb * 16 * 72 * 2);
                #pragma unroll
                for (int nf = 0; nf < 4; nf++)
                    mma16816h(acc[hh][nf], ah, bv[nf]);
            }
        }
        __syncthreads();   // MMA done: V parity (t&1) free for tile t+2

        if (t + 2 < 16) issue_tile(t + 2);
    }

    // ---- epilogue: normalize, write ctx fp16 -------------------------------
    const int qrow = lane >> 2;
    const int qcol = (lane & 3) << 1;
    #pragma unroll
    for (int hh = 0; hh < 2; hh++)
        #pragma unroll
        for (int half = 0; half < 2; half++) {
            int r = wr * 16 + half * 8 + qrow;
            float inv = 1.0f / sSum[hh * 64 + r];
            long obase = ((long)b * N_SEQ + i0 + r) * DIM + (hg * 2 + hh) * HD;
            #pragma unroll
            for (int nf = 0; nf < 4; nf++) {
                int n = wc * 32 + nf * 8 + qcol;
                *(uint32_t*)&ctx[obase + n] =
                    pack_h2(acc[hh][nf][half * 2 + 0] * inv,
                            acc[hh][nf][half * 2 + 1] * inv);
            }
        }
}

// ---------------------------------------------------------------------------
extern "C" void kernel_launch(void* const* d_in, const int* in_sizes, int n_in,
                              void* d_out, int out_size)
{
    const float* x      = (const float*)d_in[0];
    const float* W_qkv  = (const float*)d_in[1];
    const float* W_v    = (const float*)d_in[2];
    const float* W_proj = (const float*)d_in[3];
    const float* b_proj = (const float*)d_in[4];
    const float* mixl   = (const float*)d_in[5];
    float* out = (float*)d_out;

    __half *px16, *pWq, *pWv, *pWp, *pYh, *pV16, *pc16, *pS4h, *pVt;
    cudaGetSymbolAddress((void**)&px16, g_x16);
    cudaGetSymbolAddress((void**)&pWq,  g_Wq16);
    cudaGetSymbolAddress((void**)&pWv,  g_Wv16);
    cudaGetSymbolAddress((void**)&pWp,  g_Wp16);
    cudaGetSymbolAddress((void**)&pYh,  g_Yh);
    cudaGetSymbolAddress((void**)&pV16, g_V16);
    cudaGetSymbolAddress((void**)&pc16, g_c16);
    cudaGetSymbolAddress((void**)&pS4h, g_S4h);
    cudaGetSymbolAddress((void**)&pVt,  g_Vt);

    static cudaStream_t s1 = nullptr;
    static cudaEvent_t evX = nullptr, evJ = nullptr;
    static bool attrDone = false;
    if (!attrDone) {
        cudaFuncSetAttribute(attn_kernel,
                             cudaFuncAttributeMaxDynamicSharedMemorySize, ATTN_SMEM);
        cudaStreamCreateWithFlags(&s1, cudaStreamNonBlocking);
        cudaEventCreateWithFlags(&evX, cudaEventDisableTiming);
        cudaEventCreateWithFlags(&evJ, cudaEventDisableTiming);
        attrDone = true;
    }

    dim3 blk(256);
    const int NX4 = B_SZ * N_SEQ * DIM / 4;
    const int NW4 = DIM * DIM / 4;
    const int NQ4 = 512 * DIM / 4;

    // ---- main: x -> fp16, then fork ---------------------------------------
    cvt16<<<(NX4 + 255) / 256, blk>>>(x, px16, NX4);
    cudaEventRecord(evX, 0);
    cudaStreamWaitEvent(s1, evX, 0);

    // ---- side stream: Wv cvt -> V -> vconvert -----------------------------
    cvt16<<<(NW4 + 255) / 256, blk, 0, s1>>>(W_v, pWv, NW4);
    gemm16<<<dim3(6, 64, 1), blk, GSMEM, s1>>>(
        px16, pWv, nullptr, pV16, nullptr, DIM, DIM, DIM, DIM, 1.0f,
        0, 0, 0, 0, 0, 1);
    vconvert<<<dim3(16, 96, 1), blk, 0, s1>>>(pV16, pVt);
    cudaEventRecord(evJ, s1);

    // ---- main: Wq cvt -> Y -> S4 -> Wp cvt --------------------------------
    cvt16<<<(NQ4 + 255) / 256, blk>>>(W_qkv, pWq, NQ4);
    gemm16<<<dim3(4, 64, 1), blk, GSMEM>>>(
        px16, pWq, nullptr, pYh, nullptr, DIM, DIM, DIM, 512, 1.0f,
        0, 0, 0, 0, 0, 1);
    gemm16<<<dim3(8, 8, B_SZ * KG), blk, GSMEM>>>(
        pYh, pYh + 256, nullptr, pS4h, nullptr, HD, 512, 512, N_SEQ, 0.125f,
        (long)N_SEQ * 512, 64, (long)N_SEQ * 512, 64, (long)N_SEQ * N_SEQ, KG);
    cvt16<<<(NW4 + 255) / 256, blk>>>(W_proj, pWp, NW4);

    // ---- join, then attn + proj on main -----------------------------------
    cudaStreamWaitEvent(0, evJ, 0);
    attn_kernel<<<dim3(16, 6, 8), blk, ATTN_SMEM>>>(pS4h, pVt, mixl, pc16);
    gemm16<<<dim3(6, 64, 1), blk, GSMEM>>>(
        pc16, pWp, out, nullptr, b_proj, DIM, DIM, DIM, DIM, 1.0f,
        0, 0, 0, 0, 0, 1);
}

// round 17
// speedup vs baseline: 1.1392x; 1.1392x over previous
#include <cuda_runtime.h>
#include <cuda_bf16.h>
#include <cuda_fp16.h>
#include <cstdint>

// ---------------------------------------------------------------------------
// FiSHAttention: B=8, N=1024, dim=p=768, HEAD_DIM=64, K_GLOBAL=4, H_eff=12
// Pure-fp16 tensor pipeline + dual streams + MUFU exp.
// attn v10: 2 CTA/SM kept; S4 stage double-buffered with ~2-tile prefetch
// lead, V single-buffered but prefetched across phase A. 3 barriers/tile.
// Error model (calibrated): out_err ~= 0.44*unit-rounding/fp16 operand;
// measured 5.2e-4, margin ~1.9x.
// ---------------------------------------------------------------------------

#define B_SZ   8
#define N_SEQ  1024
#define DIM    768
#define KG     4
#define HD     64
#define HEFF   12

__device__ __half g_x16[B_SZ * N_SEQ * DIM];
__device__ __half g_Wq16[512 * DIM];
__device__ __half g_Wv16[DIM * DIM];
__device__ __half g_Wp16[DIM * DIM];
__device__ __half g_Yh [B_SZ * N_SEQ * 512];
__device__ __half g_V16[B_SZ * N_SEQ * DIM];
__device__ __half g_c16[B_SZ * N_SEQ * DIM];
__device__ __half g_S4h[(size_t)B_SZ * KG * N_SEQ * N_SEQ];   // 64 MB
__device__ __half g_Vt [(size_t)B_SZ * HEFF * HD * N_SEQ];

// ------------------------------ helpers ------------------------------------
__device__ __forceinline__ uint32_t smem_u32(const void* p) {
    uint32_t a;
    asm("{ .reg .u64 t; cvta.to.shared.u64 t, %1; cvt.u32.u64 %0, t; }"
        : "=r"(a) : "l"(p));
    return a;
}
__device__ __forceinline__ void ldsm_x4(uint32_t& r0, uint32_t& r1,
                                        uint32_t& r2, uint32_t& r3, uint32_t addr) {
    asm volatile("ldmatrix.sync.aligned.m8n8.x4.shared.b16 {%0,%1,%2,%3}, [%4];"
        : "=r"(r0), "=r"(r1), "=r"(r2), "=r"(r3) : "r"(addr));
}
__device__ __forceinline__ void mma16816h(float* c, const uint32_t* a,
                                          const uint32_t* b) {
    asm volatile("mma.sync.aligned.m16n8k16.row.col.f32.f16.f16.f32 "
        "{%0,%1,%2,%3}, {%4,%5,%6,%7}, {%8,%9}, {%0,%1,%2,%3};"
        : "+f"(c[0]), "+f"(c[1]), "+f"(c[2]), "+f"(c[3])
        : "r"(a[0]), "r"(a[1]), "r"(a[2]), "r"(a[3]), "r"(b[0]), "r"(b[1]));
}
__device__ __forceinline__ void cp_async16(uint32_t s, const void* g) {
    asm volatile("cp.async.cg.shared.global [%0], [%1], 16;" :: "r"(s), "l"(g));
}
__device__ __forceinline__ void cp_commit() {
    asm volatile("cp.async.commit_group;" ::: "memory");
}
template<int N> __device__ __forceinline__ void cp_wait() {
    asm volatile("cp.async.wait_group %0;" :: "n"(N) : "memory");
}
__device__ __forceinline__ uint32_t pack_h2(float x, float y) {
    return ((uint32_t)__half_as_ushort(__float2half(y)) << 16)
         | __half_as_ushort(__float2half(x));
}
__device__ __forceinline__ float mufu_exp2(float y) {
    float r;
    asm("ex2.approx.f32 %0, %1;" : "=f"(r) : "f"(y));
    return r;
}

#define BKC  32
#define TSTR 40
#define GTB  (128 * TSTR * 2)
#define GSMEM (4 * GTB)

// ===========================================================================
// cvt16: f32 -> fp16 elementwise.
// ===========================================================================
__global__ __launch_bounds__(256) void cvt16(
    const float* __restrict__ in, __half* __restrict__ o, int n4)
{
    int i = blockIdx.x * 256 + threadIdx.x;
    if (i >= n4) return;
    float4 v = ((const float4*)in)[i];
    uint2 h;
    h.x = pack_h2(v.x, v.y);
    h.y = pack_h2(v.z, v.w);
    ((uint2*)o)[i] = h;
}

// ===========================================================================
// Unified pure-fp16 TN GEMM, cp.async 2-stage double-buffered.
// ===========================================================================
__global__ __launch_bounds__(256) void gemm16(
    const __half* __restrict__ A, const __half* __restrict__ B,
    float* __restrict__ Cf, __half* __restrict__ Ch,
    const float* __restrict__ bias,
    int K, int lda, int ldb, int ldc, float alpha,
    long sAo, long sAi, long sBo, long sBi, long sC, int innerMod)
{
    {
        int z = blockIdx.z;
        int outer = z / innerMod;
        int inner = z - outer * innerMod;
        A += (long)outer * sAo + (long)inner * sAi;
        B += (long)outer * sBo + (long)inner * sBi;
        if (Cf) Cf += (long)z * sC;
        if (Ch) Ch += (long)z * sC;
    }
    const int row0 = blockIdx.y * 128;
    const int col0 = blockIdx.x * 128;

    extern __shared__ char dsm[];
    const uint32_t base = smem_u32(dsm);

    const int tid  = threadIdx.x;
    const int wid  = tid >> 5;
    const int lane = tid & 31;
    const int wm   = wid >> 1;
    const int wn   = wid & 1;
    const int a_r = lane & 15;
    const int a_k = (lane >> 4) << 3;
    const int b_r = (lane & 7) + ((lane >> 4) << 3);
    const int b_k = ((lane >> 3) & 1) << 3;

    float acc[2][8][4];
    #pragma unroll
    for (int i = 0; i < 2; i++)
        #pragma unroll
        for (int j = 0; j < 8; j++)
            #pragma unroll
            for (int q = 0; q < 4; q++) acc[i][j][q] = 0.0f;

    auto issue = [&](int t) {
        const uint32_t sb = base + (uint32_t)(t & 1) * (2 * GTB);
        #pragma unroll
        for (int it = 0; it < 2; it++) {
            int idx = it * 256 + tid;
            int r = idx >> 2, q = (idx & 3) << 3;
            cp_async16(sb + (uint32_t)(r * TSTR + q) * 2,
                       &A[(long)(row0 + r) * lda + t * BKC + q]);
        }
        #pragma unroll
        for (int it = 0; it < 2; it++) {
            int idx = it * 256 + tid;
            int r = idx >> 2, q = (idx & 3) << 3;
            cp_async16(sb + GTB + (uint32_t)(r * TSTR + q) * 2,
                       &B[(long)(col0 + r) * ldb + t * BKC + q]);
        }
        cp_commit();
    };

    const int nch = K / BKC;
    issue(0);

    for (int t = 0; t < nch; t++) {
        if (t + 1 < nch) {
            issue(t + 1);
            cp_wait<1>();
        } else {
            cp_wait<0>();
        }
        __syncthreads();

        const uint32_t uA = base + (uint32_t)(t & 1) * (2 * GTB);
        const uint32_t uB = uA + GTB;

        #pragma unroll
        for (int ks = 0; ks < 2; ks++) {
            const int k0 = ks * 16;
            const uint32_t aoff = (uint32_t)((wm * 32 + a_r) * TSTR + k0 + a_k) * 2;
            const uint32_t boff = (uint32_t)((wn * 64 + b_r) * TSTR + k0 + b_k) * 2;
            uint32_t af[2][4];
            ldsm_x4(af[0][0], af[0][1], af[0][2], af[0][3], uA + aoff);
            ldsm_x4(af[1][0], af[1][1], af[1][2], af[1][3], uA + aoff + 16 * TSTR * 2);
            uint32_t bv[8][2];
            #pragma unroll
            for (int nb = 0; nb < 4; nb++)
                ldsm_x4(bv[2*nb][0], bv[2*nb][1], bv[2*nb+1][0], bv[2*nb+1][1],
                        uB + boff + nb * 16 * TSTR * 2);
            #pragma unroll
            for (int mf = 0; mf < 2; mf++)
                #pragma unroll
                for (int nf = 0; nf < 8; nf++)
                    mma16816h(acc[mf][nf], af[mf], bv[nf]);
        }
        __syncthreads();
    }

    const int qrow = lane >> 2;
    const int qcol = (lane & 3) << 1;
    #pragma unroll
    for (int mf = 0; mf < 2; mf++)
        #pragma unroll
        for (int half = 0; half < 2; half++) {
            long r = row0 + wm * 32 + mf * 16 + half * 8 + qrow;
            #pragma unroll
            for (int nf = 0; nf < 8; nf++) {
                int n = col0 + wn * 64 + nf * 8 + qcol;
                float ox = alpha * acc[mf][nf][half * 2 + 0];
                float oy = alpha * acc[mf][nf][half * 2 + 1];
                if (Cf) {
                    float2 o;
                    o.x = ox; o.y = oy;
                    if (bias) { o.x += bias[n]; o.y += bias[n + 1]; }
                    *(float2*)&Cf[r * ldc + n] = o;
                } else {
                    *(uint32_t*)&Ch[r * ldc + n] = pack_h2(ox, oy);
                }
            }
        }
}

// ===========================================================================
// V transpose (fp16 in/out).
// ===========================================================================
__global__ __launch_bounds__(256) void vconvert(
    const __half* __restrict__ V, __half* __restrict__ Vt)
{
    const int j0   = blockIdx.x * 64;
    const int bhid = blockIdx.y;
    const int b    = bhid / HEFF;
    const int h    = bhid - b * HEFF;

    __shared__ __half sT[64][72];
    const int tid = threadIdx.x;

    #pragma unroll
    for (int it = 0; it < 4; it++) {
        int e = it * 256 + tid;
        int j = e >> 4, dq = (e & 15) << 2;
        uint2 u = *(const uint2*)&V[((long)b * N_SEQ + j0 + j) * DIM + h * HD + dq];
        __half2 a = *(__half2*)&u.x;
        __half2 c = *(__half2*)&u.y;
        sT[dq + 0][j] = __low2half(a);  sT[dq + 1][j] = __high2half(a);
        sT[dq + 2][j] = __low2half(c);  sT[dq + 3][j] = __high2half(c);
    }
    __syncthreads();

    const int d = tid >> 2, jseg = (tid & 3) << 4;
    size_t dst = ((size_t)bhid * HD + d) * N_SEQ + j0 + jseg;
    *(uint4*)&Vt[dst]     = *(uint4*)&sT[d][jseg];
    *(uint4*)&Vt[dst + 8] = *(uint4*)&sT[d][jseg + 8];
}

// ===========================================================================
// Attention v10: 2 CTA/SM. Stage double-buffered (issued at phase-A(t) end,
// ~2 tiles of lead); V single-buffered (issued post-MMA, lands across next
// phase A). Groups per tile: S then V; per-thread FIFO schedule verified:
//   prologue: S0 | S1 | V0
//   tile t:  [t==0: wait<=2]  phaseA(t)  sync
//            [t+2<16: issue S(t+2); wait<=1 | else wait<=0]  sync
//            MMA(t)  sync  [t+1<16: issue V(t+1)]
// smem: V 2x9216 | P 2x9216 | stage 2x(4x9216) = ~111KB -> 2 CTA/SM.
// ===========================================================================
#define PBY 9216
#define SPLB 9216                     // stage plane: 64 x 72 fp16 (padded)
#define SBUFB (4 * SPLB)              // 36864 per stage buffer
#define OFF_V 0                       // [head] 2 x PBY
#define OFF_P (2 * PBY)               // 18432
#define OFF_S (4 * PBY)               // 36864
#define OFF_SUM (OFF_S + 2 * SBUFB)   // 110592
#define OFF_MIX (OFF_SUM + 512)
#define ATTN_SMEM (OFF_MIX + 64)

__global__ __launch_bounds__(256, 2) void attn_kernel(
    const __half* __restrict__ S4, const __half* __restrict__ Vt,
    const float* __restrict__ mixl, __half* __restrict__ ctx)
{
    const int ib = blockIdx.x;
    const int hg = blockIdx.y;
    const int b  = blockIdx.z;

    extern __shared__ char sm[];
    const uint32_t sb = smem_u32(sm);
    float* sSum = (float*)(sm + OFF_SUM);
    float* sMix = (float*)(sm + OFF_MIX);

    const int tid  = threadIdx.x;
    const int wid  = tid >> 5;
    const int lane = tid & 31;
    const int wr   = wid >> 1;
    const int wc   = wid & 1;
    const int a_r  = lane & 15;
    const int a_k  = (lane >> 4) << 3;
    const int b_r  = (lane & 7) + ((lane >> 4) << 3);
    const int b_k  = ((lane >> 3) & 1) << 3;

    if (tid < 128) sSum[tid] = 0.0f;
    if (tid < 8) {
        int hh = tid >> 2, k = tid & 3;
        const float* ml = mixl + (hg * 2 + hh) * 4;
        float l0 = ml[0], l1 = ml[1], l2 = ml[2], l3 = ml[3];
        const float L2E = 1.4426950408889634f;
        float m  = fmaxf(fmaxf(l0, l1), fmaxf(l2, l3));
        float e0 = mufu_exp2((l0 - m) * L2E), e1 = mufu_exp2((l1 - m) * L2E);
        float e2 = mufu_exp2((l2 - m) * L2E), e3 = mufu_exp2((l3 - m) * L2E);
        float s  = e0 + e1 + e2 + e3;
        float mine = (k == 0) ? e0 : (k == 1) ? e1 : (k == 2) ? e2 : e3;
        sMix[hh * 4 + k] = (mine / s) * L2E;
    }

    const int i0   = ib * 64;
    const int arow = tid >> 2;
    const int aq   = tid & 3;
    const __half* S4b = S4 + (size_t)b * KG * N_SEQ * N_SEQ;
    const long   PL  = (long)N_SEQ * N_SEQ;
    const size_t vbase0 = ((size_t)(b * HEFF + hg * 2 + 0)) * HD * N_SEQ;
    const size_t vbase1 = ((size_t)(b * HEFF + hg * 2 + 1)) * HD * N_SEQ;

    auto issue_stage = [&](int jt) {
        const int j0 = jt * 64;
        const uint32_t sdst = sb + OFF_S + (uint32_t)(jt & 1) * SBUFB;
        #pragma unroll
        for (int it = 0; it < 8; it++) {           // 2048 x 16B
            int idx = it * 256 + tid;
            int p  = idx >> 9;
            int r  = (idx >> 3) & 63;
            int q  = idx & 7;
            const __half* g = S4b + (size_t)p * PL
                            + (long)(i0 + r) * N_SEQ + j0 + q * 8;
            cp_async16(sdst + (uint32_t)(p * SPLB) + (uint32_t)(r * 72 + q * 8) * 2, g);
        }
        cp_commit();
    };
    auto issue_v = [&](int jt) {
        const int j0 = jt * 64;
        #pragma unroll
        for (int it = 0; it < 4; it++) {           // 1024 x 16B
            int idx = it * 256 + tid;
            int hh = idx >> 9;
            int r  = (idx >> 3) & 63;
            int q  = idx & 7;
            size_t so = (hh ? vbase1 : vbase0) + (size_t)r * N_SEQ + j0 + q * 8;
            cp_async16(sb + OFF_V + (uint32_t)hh * PBY
                          + (uint32_t)(r * 72 + q * 8) * 2, &Vt[so]);
        }
        cp_commit();
    };

    float acc[2][4][4];
    #pragma unroll
    for (int i = 0; i < 2; i++)
        #pragma unroll
        for (int j = 0; j < 4; j++)
            #pragma unroll
            for (int q = 0; q < 4; q++) acc[i][j][q] = 0.0f;

    issue_stage(0);
    issue_stage(1);
    issue_v(0);

    for (int t = 0; t < 16; t++) {
        if (t == 0) cp_wait<2>();
        __syncthreads();   // publishes S(t) (and, t>0, orders prev-MMA P reads)

        // ---- phase A: combine from stage + MUFU exp2, store P fp16 ---------
        {
            const float mx00 = sMix[0], mx01 = sMix[1], mx02 = sMix[2], mx03 = sMix[3];
            const float mx10 = sMix[4], mx11 = sMix[5], mx12 = sMix[6], mx13 = sMix[7];
            const char* sst = sm + OFF_S + (uint32_t)(t & 1) * SBUFB
                            + (uint32_t)(arow * 72 + aq * 16) * 2;
            uint32_t pr[4][8];
            #pragma unroll
            for (int p = 0; p < 4; p++) {
                *(uint4*)&pr[p][0] = *(const uint4*)(sst + p * SPLB);
                *(uint4*)&pr[p][4] = *(const uint4*)(sst + p * SPLB + 16);
            }
            float s0 = 0.0f, s1 = 0.0f;
            #pragma unroll
            for (int c = 0; c < 4; c++) {
                float2 fa0 = __half22float2(*(__half2*)&pr[0][2*c]);
                float2 fa1 = __half22float2(*(__half2*)&pr[0][2*c+1]);
                float2 f10 = __half22float2(*(__half2*)&pr[1][2*c]);
                float2 f11 = __half22float2(*(__half2*)&pr[1][2*c+1]);
                float2 f20 = __half22float2(*(__half2*)&pr[2][2*c]);
                float2 f21 = __half22float2(*(__half2*)&pr[2][2*c+1]);
                float2 f30 = __half22float2(*(__half2*)&pr[3][2*c]);
                float2 f31 = __half22float2(*(__half2*)&pr[3][2*c+1]);
                const uint32_t po = (uint32_t)(arow * 72 + aq * 16 + c * 4) * 2;
                #pragma unroll
                for (int hh = 0; hh < 2; hh++) {
                    float m0 = hh ? mx10 : mx00, m1 = hh ? mx11 : mx01;
                    float m2 = hh ? mx12 : mx02, m3 = hh ? mx13 : mx03;
                    float q0 = mufu_exp2(fmaf(m3, f30.x, fmaf(m2, f20.x, fmaf(m1, f10.x, m0 * fa0.x))));
                    float q1 = mufu_exp2(fmaf(m3, f30.y, fmaf(m2, f20.y, fmaf(m1, f10.y, m0 * fa0.y))));
                    float q2 = mufu_exp2(fmaf(m3, f31.x, fmaf(m2, f21.x, fmaf(m1, f11.x, m0 * fa1.x))));
                    float q3 = mufu_exp2(fmaf(m3, f31.y, fmaf(m2, f21.y, fmaf(m1, f11.y, m0 * fa1.y))));
                    if (hh) s1 += (q0 + q1) + (q2 + q3);
                    else    s0 += (q0 + q1) + (q2 + q3);
                    uint2 hv;
                    hv.x = pack_h2(q0, q1);
                    hv.y = pack_h2(q2, q3);
                    *(uint2*)(sm + OFF_P + hh * PBY + po) = hv;
                }
            }
            s0 += __shfl_xor_sync(0xffffffffu, s0, 1);
            s0 += __shfl_xor_sync(0xffffffffu, s0, 2);
            s1 += __shfl_xor_sync(0xffffffffu, s1, 1);
            s1 += __shfl_xor_sync(0xffffffffu, s1, 2);
            if (aq == 0) {
                sSum[arow]      += s0;
                sSum[64 + arow] += s1;
            }
        }
        __syncthreads();   // P published; stage(t) consumed (same parity reusable)

        if (t + 2 < 16) {
            issue_stage(t + 2);
            cp_wait<1>();   // completes S(t+1) and V(t)
        } else {
            cp_wait<0>();
        }
        __syncthreads();   // publish V(t)

        // ---- MMA: both heads, 1-pass fp16 (P @ V) --------------------------
        #pragma unroll
        for (int hh = 0; hh < 2; hh++) {
            const uint32_t uP = sb + OFF_P + hh * PBY;
            const uint32_t uV = sb + OFF_V + (uint32_t)hh * PBY;
            #pragma unroll
            for (int ks = 0; ks < 4; ks++) {
                const int k0 = ks * 16;
                const uint32_t aoff = (uint32_t)((wr * 16 + a_r) * 72 + k0 + a_k) * 2;
                const uint32_t boff = (uint32_t)((wc * 32 + b_r) * 72 + k0 + b_k) * 2;
                uint32_t ah[4];
                ldsm_x4(ah[0], ah[1], ah[2], ah[3], uP + aoff);
                uint32_t bv[4][2];
                #pragma unroll
                for (int nb = 0; nb < 2; nb++)
                    ldsm_x4(bv[2*nb][0], bv[2*nb][1], bv[2*nb+1][0], bv[2*nb+1][1],
                            uV + boff + nb * 16 * 72 * 2);
                #pragma unroll
                for (int nf = 0; nf < 4; nf++)
                    mma16816h(acc[hh][nf], ah, bv[nf]);
            }
        }
        __syncthreads();   // MMA done: V buffer reusable

        if (t + 1 < 16) issue_v(t + 1);
    }

    // ---- epilogue: normalize, write ctx fp16 -------------------------------
    const int qrow = lane >> 2;
    const int qcol = (lane & 3) << 1;
    #pragma unroll
    for (int hh = 0; hh < 2; hh++)
        #pragma unroll
        for (int half = 0; half < 2; half++) {
            int r = wr * 16 + half * 8 + qrow;
            float inv = 1.0f / sSum[hh * 64 + r];
            long obase = ((long)b * N_SEQ + i0 + r) * DIM + (hg * 2 + hh) * HD;
            #pragma unroll
            for (int nf = 0; nf < 4; nf++) {
                int n = wc * 32 + nf * 8 + qcol;
                *(uint32_t*)&ctx[obase + n] =
                    pack_h2(acc[hh][nf][half * 2 + 0] * inv,
                            acc[hh][nf][half * 2 + 1] * inv);
            }
        }
}

// ---------------------------------------------------------------------------
extern "C" void kernel_launch(void* const* d_in, const int* in_sizes, int n_in,
                              void* d_out, int out_size)
{
    const float* x      = (const float*)d_in[0];
    const float* W_qkv  = (const float*)d_in[1];
    const float* W_v    = (const float*)d_in[2];
    const float* W_proj = (const float*)d_in[3];
    const float* b_proj = (const float*)d_in[4];
    const float* mixl   = (const float*)d_in[5];
    float* out = (float*)d_out;

    __half *px16, *pWq, *pWv, *pWp, *pYh, *pV16, *pc16, *pS4h, *pVt;
    cudaGetSymbolAddress((void**)&px16, g_x16);
    cudaGetSymbolAddress((void**)&pWq,  g_Wq16);
    cudaGetSymbolAddress((void**)&pWv,  g_Wv16);
    cudaGetSymbolAddress((void**)&pWp,  g_Wp16);
    cudaGetSymbolAddress((void**)&pYh,  g_Yh);
    cudaGetSymbolAddress((void**)&pV16, g_V16);
    cudaGetSymbolAddress((void**)&pc16, g_c16);
    cudaGetSymbolAddress((void**)&pS4h, g_S4h);
    cudaGetSymbolAddress((void**)&pVt,  g_Vt);

    static cudaStream_t s1 = nullptr;
    static cudaEvent_t evX = nullptr, evJ = nullptr;
    static bool attrDone = false;
    if (!attrDone) {
        cudaFuncSetAttribute(attn_kernel,
                             cudaFuncAttributeMaxDynamicSharedMemorySize, ATTN_SMEM);
        cudaStreamCreateWithFlags(&s1, cudaStreamNonBlocking);
        cudaEventCreateWithFlags(&evX, cudaEventDisableTiming);
        cudaEventCreateWithFlags(&evJ, cudaEventDisableTiming);
        attrDone = true;
    }

    dim3 blk(256);
    const int NX4 = B_SZ * N_SEQ * DIM / 4;
    const int NW4 = DIM * DIM / 4;
    const int NQ4 = 512 * DIM / 4;

    // ---- main: x -> fp16, then fork ---------------------------------------
    cvt16<<<(NX4 + 255) / 256, blk>>>(x, px16, NX4);
    cudaEventRecord(evX, 0);
    cudaStreamWaitEvent(s1, evX, 0);

    // ---- side stream: Wv cvt -> V -> vconvert -----------------------------
    cvt16<<<(NW4 + 255) / 256, blk, 0, s1>>>(W_v, pWv, NW4);
    gemm16<<<dim3(6, 64, 1), blk, GSMEM, s1>>>(
        px16, pWv, nullptr, pV16, nullptr, DIM, DIM, DIM, DIM, 1.0f,
        0, 0, 0, 0, 0, 1);
    vconvert<<<dim3(16, 96, 1), blk, 0, s1>>>(pV16, pVt);
    cudaEventRecord(evJ, s1);

    // ---- main: Wq cvt -> Y -> S4 -> Wp cvt --------------------------------
    cvt16<<<(NQ4 + 255) / 256, blk>>>(W_qkv, pWq, NQ4);
    gemm16<<<dim3(4, 64, 1), blk, GSMEM>>>(
        px16, pWq, nullptr, pYh, nullptr, DIM, DIM, DIM, 512, 1.0f,
        0, 0, 0, 0, 0, 1);
    gemm16<<<dim3(8, 8, B_SZ * KG), blk, GSMEM>>>(
        pYh, pYh + 256, nullptr, pS4h, nullptr, HD, 512, 512, N_SEQ, 0.125f,
        (long)N_SEQ * 512, 64, (long)N_SEQ * 512, 64, (long)N_SEQ * N_SEQ, KG);
    cvt16<<<(NW4 + 255) / 256, blk>>>(W_proj, pWp, NW4);

    // ---- join, then attn + proj on main -----------------------------------
    cudaStreamWaitEvent(0, evJ, 0);
    attn_kernel<<<dim3(16, 6, 8), blk, ATTN_SMEM>>>(pS4h, pVt, mixl, pc16);
    gemm16<<<dim3(6, 64, 1), blk, GSMEM>>>(
        pc16, pWp, out, nullptr, b_proj, DIM, DIM, DIM, DIM, 1.0f,
        0, 0, 0, 0, 0, 1);
}